// round 1
// baseline (speedup 1.0000x reference)
#include <cuda_runtime.h>

#define NB 4
#define NT 3072
#define ND 1024
#define NH 16
#define HD 64
#define TK 1025   // pooled K/V length: 1 + 3072/3

// ---------------- scratch (device globals: no allocations allowed) ----------
__device__ float g_ktmp[NB * TK * ND];   // pooled stream [B][TK][D]
__device__ float g_q[NB * NT * ND];      // Q projected  [B][T][D]  (D = h*64+d)
__device__ float g_k[NB * TK * ND];
__device__ float g_v[NB * TK * ND];
__device__ float g_o[NB * NT * ND];      // attention output, pre-Wo
__device__ float g_wc2[ND * 3 * ND];     // Wconv transposed: [o][kw*1024 + i]

// ---------------- small prep kernels ----------------------------------------
__global__ void transpose_wconv(const float* __restrict__ Wc, float* __restrict__ out) {
    int idx = blockIdx.x * 256 + threadIdx.x;           // over 1024*3072
    if (idx >= ND * 3 * ND) return;
    int o = idx / (3 * ND);
    int r = idx - o * 3 * ND;
    int kw = r >> 10;            // r / 1024
    int i  = r & 1023;
    out[idx] = Wc[(size_t)o * 3 * ND + (size_t)i * 3 + kw];
}

__global__ void copy_row0(const float* __restrict__ x, float* __restrict__ ktmp) {
    int idx = blockIdx.x * 256 + threadIdx.x;           // over 4*1024
    if (idx >= NB * ND) return;
    int b = idx >> 10, i = idx & 1023;
    ktmp[(size_t)b * TK * ND + i] = x[(size_t)b * NT * ND + i];
}

// ---------------- generic NT SGEMM: C[m][n] = sum_k A[m][k] * W[n][k] --------
// N fixed at 1024. 128x128 tile, BK=8, 256 threads, 8x8 per thread.
// MODE 0: A rows contiguous stride K, C rows contiguous stride 1024.
// MODE 1 (conv): A row m -> x + (b*3072 + 3j)*1024 (b=m>>10, j=m&1023), K=3072;
//                C row m -> ktmp + (b*1025 + j + 1)*1024.
template <int MODE>
__global__ void __launch_bounds__(256)
gemm_nt(const float* __restrict__ A, const float* __restrict__ W,
        float* __restrict__ C, const float* __restrict__ bias, int M, int K) {
    __shared__ float As[8][128];
    __shared__ float Bs[8][128];

    int tid = threadIdx.x;
    int bm = blockIdx.y * 128;
    int bn = blockIdx.x * 128;

    int lr = tid >> 1;          // 0..127: tile row for global loads
    int lk = (tid & 1) * 4;     // 0 or 4: k sub-offset
    int tx = tid & 15, ty = tid >> 4;

    int am = bm + lr;
    bool avalid = am < M;
    const float* Arow;
    if (MODE == 0) Arow = A + (size_t)am * K;
    else           Arow = A + ((size_t)(am >> 10) * NT + (size_t)(am & 1023) * 3) * ND;
    const float* Brow = W + (size_t)(bn + lr) * K;   // N=1024 -> always valid

    float acc[8][8];
#pragma unroll
    for (int i = 0; i < 8; i++)
#pragma unroll
        for (int j = 0; j < 8; j++) acc[i][j] = 0.f;

    for (int k0 = 0; k0 < K; k0 += 8) {
        float4 a4 = avalid ? *(const float4*)(Arow + k0 + lk) : make_float4(0.f, 0.f, 0.f, 0.f);
        float4 b4 = *(const float4*)(Brow + k0 + lk);
        As[lk + 0][lr] = a4.x; As[lk + 1][lr] = a4.y; As[lk + 2][lr] = a4.z; As[lk + 3][lr] = a4.w;
        Bs[lk + 0][lr] = b4.x; Bs[lk + 1][lr] = b4.y; Bs[lk + 2][lr] = b4.z; Bs[lk + 3][lr] = b4.w;
        __syncthreads();
#pragma unroll
        for (int kk = 0; kk < 8; kk++) {
            float4 a0 = *(const float4*)&As[kk][ty * 4];
            float4 a1 = *(const float4*)&As[kk][ty * 4 + 64];
            float4 b0 = *(const float4*)&Bs[kk][tx * 4];
            float4 b1 = *(const float4*)&Bs[kk][tx * 4 + 64];
            float av[8] = {a0.x, a0.y, a0.z, a0.w, a1.x, a1.y, a1.z, a1.w};
            float bv[8] = {b0.x, b0.y, b0.z, b0.w, b1.x, b1.y, b1.z, b1.w};
#pragma unroll
            for (int i = 0; i < 8; i++)
#pragma unroll
                for (int j = 0; j < 8; j++) acc[i][j] += av[i] * bv[j];
        }
        __syncthreads();
    }

#pragma unroll
    for (int ih = 0; ih < 2; ih++)
#pragma unroll
        for (int ii = 0; ii < 4; ii++) {
            int rm = bm + ih * 64 + ty * 4 + ii;
            if (rm >= M) continue;
            float* crow;
            if (MODE == 0) crow = C + (size_t)rm * ND;
            else           crow = C + ((size_t)(rm >> 10) * TK + (rm & 1023) + 1) * ND;
#pragma unroll
            for (int jh = 0; jh < 2; jh++) {
                int cn = bn + jh * 64 + tx * 4;
                float4 r;
                r.x = acc[ih * 4 + ii][jh * 4 + 0];
                r.y = acc[ih * 4 + ii][jh * 4 + 1];
                r.z = acc[ih * 4 + ii][jh * 4 + 2];
                r.w = acc[ih * 4 + ii][jh * 4 + 3];
                if (bias) {
                    float4 bb = *(const float4*)(bias + cn);
                    r.x += bb.x; r.y += bb.y; r.z += bb.z; r.w += bb.w;
                }
                *(float4*)(crow + cn) = r;
            }
        }
}

// ---------------- flash attention -------------------------------------------
// grid: (T/128, B*H). 128 threads; thread t owns query q = q0+t.
// Mask: key k allowed iff 3k <= q  (k <= q/3). Skipped keys == exp underflow.
__global__ void __launch_bounds__(128)
flash_attn(const float* __restrict__ Q, const float* __restrict__ Kb,
           const float* __restrict__ Vb, float* __restrict__ O) {
    __shared__ float Ks[64][64];
    __shared__ float Vs[64][64];

    int bh = blockIdx.y;
    int b = bh >> 4, h = bh & 15;
    int q0 = blockIdx.x * 128;
    int t = threadIdx.x;
    int q = q0 + t;

    const float* qrow = Q + ((size_t)(b * NT + q)) * ND + h * HD;
    float qr[64];
#pragma unroll
    for (int d4 = 0; d4 < 16; d4++) {
        float4 f = ((const float4*)qrow)[d4];
        qr[d4 * 4 + 0] = f.x; qr[d4 * 4 + 1] = f.y;
        qr[d4 * 4 + 2] = f.z; qr[d4 * 4 + 3] = f.w;
    }

    float m_i = -1e30f, l_i = 0.f;
    float acc[64];
#pragma unroll
    for (int d = 0; d < 64; d++) acc[d] = 0.f;

    int kmax = q / 3;                       // last allowed key for this query
    int kmax_blk = (q0 + 127) / 3;          // last allowed key in the block
    int ntiles = kmax_blk / 64 + 1;

    const float* kbase = Kb + (size_t)b * TK * ND + h * HD;
    const float* vbase = Vb + (size_t)b * TK * ND + h * HD;

    for (int tile = 0; tile < ntiles; tile++) {
        int kt0 = tile * 64;
        __syncthreads();
#pragma unroll
        for (int vv = 0; vv < 8; vv++) {
            int f = t + vv * 128;
            int j = f >> 4;
            int c = (f & 15) * 4;
            *(float4*)&Ks[j][c] = *(const float4*)(kbase + (size_t)(kt0 + j) * ND + c);
            *(float4*)&Vs[j][c] = *(const float4*)(vbase + (size_t)(kt0 + j) * ND + c);
        }
        __syncthreads();

        int jcnt = kmax - kt0 + 1;
        if (jcnt > 64) jcnt = 64;
        for (int j = 0; j < jcnt; j++) {
            const float4* kr = (const float4*)Ks[j];
            float s0 = 0.f, s1 = 0.f, s2 = 0.f, s3 = 0.f;
#pragma unroll
            for (int d4 = 0; d4 < 16; d4++) {
                float4 kk = kr[d4];
                s0 += qr[d4 * 4 + 0] * kk.x;
                s1 += qr[d4 * 4 + 1] * kk.y;
                s2 += qr[d4 * 4 + 2] * kk.z;
                s3 += qr[d4 * 4 + 3] * kk.w;
            }
            float s = ((s0 + s1) + (s2 + s3)) * 0.125f;
            if (s > m_i) {
                float corr = __expf(m_i - s);
                l_i *= corr;
#pragma unroll
                for (int d = 0; d < 64; d++) acc[d] *= corr;
                m_i = s;
            }
            float p = __expf(s - m_i);
            l_i += p;
            const float4* vr = (const float4*)Vs[j];
#pragma unroll
            for (int d4 = 0; d4 < 16; d4++) {
                float4 vvv = vr[d4];
                acc[d4 * 4 + 0] += p * vvv.x;
                acc[d4 * 4 + 1] += p * vvv.y;
                acc[d4 * 4 + 2] += p * vvv.z;
                acc[d4 * 4 + 3] += p * vvv.w;
            }
        }
    }

    float inv = 1.f / l_i;
    float* orow = O + ((size_t)(b * NT + q)) * ND + h * HD;
#pragma unroll
    for (int d4 = 0; d4 < 16; d4++) {
        float4 r;
        r.x = acc[d4 * 4 + 0] * inv;
        r.y = acc[d4 * 4 + 1] * inv;
        r.z = acc[d4 * 4 + 2] * inv;
        r.w = acc[d4 * 4 + 3] * inv;
        ((float4*)orow)[d4] = r;
    }
}

// ---------------- launch ------------------------------------------------------
extern "C" void kernel_launch(void* const* d_in, const int* in_sizes, int n_in,
                              void* d_out, int out_size) {
    const float* x     = (const float*)d_in[0];
    const float* Wq    = (const float*)d_in[1];
    const float* Wk    = (const float*)d_in[2];
    const float* Wv    = (const float*)d_in[3];
    const float* Wo    = (const float*)d_in[4];
    const float* bo    = (const float*)d_in[5];
    const float* Wconv = (const float*)d_in[6];
    float* out = (float*)d_out;

    float *p_ktmp, *p_q, *p_k, *p_v, *p_o, *p_wc2;
    cudaGetSymbolAddress((void**)&p_ktmp, g_ktmp);
    cudaGetSymbolAddress((void**)&p_q,    g_q);
    cudaGetSymbolAddress((void**)&p_k,    g_k);
    cudaGetSymbolAddress((void**)&p_v,    g_v);
    cudaGetSymbolAddress((void**)&p_o,    g_o);
    cudaGetSymbolAddress((void**)&p_wc2,  g_wc2);

    // 1. transpose conv weight + prepend row 0
    transpose_wconv<<<(ND * 3 * ND + 255) / 256, 256>>>(Wconv, p_wc2);
    copy_row0<<<(NB * ND + 255) / 256, 256>>>(x, p_ktmp);

    // 2. conv pooling as GEMM: 4096 x 1024 x 3072 -> k_tmp rows 1..1024
    gemm_nt<1><<<dim3(8, 32), 256>>>(x, p_wc2, p_ktmp, nullptr, NB * ND, 3 * ND);

    // 3. projections
    gemm_nt<0><<<dim3(8, (NB * NT + 127) / 128), 256>>>(x,      Wq, p_q, nullptr, NB * NT, ND);
    gemm_nt<0><<<dim3(8, (NB * TK + 127) / 128), 256>>>(p_ktmp, Wk, p_k, nullptr, NB * TK, ND);
    gemm_nt<0><<<dim3(8, (NB * TK + 127) / 128), 256>>>(p_ktmp, Wv, p_v, nullptr, NB * TK, ND);

    // 4. masked flash attention
    flash_attn<<<dim3(NT / 128, NB * NH), 128>>>(p_q, p_k, p_v, p_o);

    // 5. output projection + bias
    gemm_nt<0><<<dim3(8, (NB * NT + 127) / 128), 256>>>(p_o, Wo, out, bo, NB * NT, ND);
}

// round 5
// speedup vs baseline: 1.6072x; 1.6072x over previous
#include <cuda_runtime.h>
#include <cuda_bf16.h>
#include <cstdint>

#define NB 4
#define NT 3072
#define ND 1024
#define NH 16
#define HD 64
#define TK 1025   // pooled K/V length: 1 + 3072/3

// GEMM tiling: 128x128 CTA tile, BK=32 (halfs), 8 warps (4 M x 2 N), warp tile 32x64
#define BM 128
#define BN 128
#define BKH 32
#define TSTRIDE 40                        // padded halfs per tile row (80 B)
#define TILE_HALFS (128 * TSTRIDE)        // 5120 halfs = 10240 B per tile
#define STAGE_HALFS (4 * TILE_HALFS)      // Ahi, Alo, Bhi, Blo
#define GEMM_SMEM (2 * STAGE_HALFS * 2)   // 81920 bytes (2 stages)

// ---------------- scratch (device globals: no allocations allowed) ----------
__device__ __align__(256) __nv_bfloat16 g_xhi[NB * NT * ND];
__device__ __align__(256) __nv_bfloat16 g_xlo[NB * NT * ND];
__device__ __align__(256) __nv_bfloat16 g_khi[NB * TK * ND];
__device__ __align__(256) __nv_bfloat16 g_klo[NB * TK * ND];
__device__ __align__(256) __nv_bfloat16 g_ohi[NB * NT * ND];
__device__ __align__(256) __nv_bfloat16 g_olo[NB * NT * ND];
__device__ __align__(256) float g_q[NB * NT * ND];
__device__ __align__(256) float g_k[NB * TK * ND];
__device__ __align__(256) float g_v[NB * TK * ND];
__device__ __align__(256) __nv_bfloat16 g_wqhi[ND * ND], g_wqlo[ND * ND];
__device__ __align__(256) __nv_bfloat16 g_wkhi[ND * ND], g_wklo[ND * ND];
__device__ __align__(256) __nv_bfloat16 g_wvhi[ND * ND], g_wvlo[ND * ND];
__device__ __align__(256) __nv_bfloat16 g_wohi[ND * ND], g_wolo[ND * ND];
__device__ __align__(256) __nv_bfloat16 g_wchi[ND * 3 * ND], g_wclo[ND * 3 * ND];

// ---------------- PTX helpers ------------------------------------------------
__device__ __forceinline__ uint32_t smem_u32(const void* p) {
    uint32_t a;
    asm("{ .reg .u64 t; cvta.to.shared.u64 t, %1; cvt.u32.u64 %0, t; }" : "=r"(a) : "l"(p));
    return a;
}
__device__ __forceinline__ void cpa16(uint32_t dst, const void* src) {
    asm volatile("cp.async.cg.shared.global [%0], [%1], 16;" :: "r"(dst), "l"(src) : "memory");
}
__device__ __forceinline__ void ldsm4(uint32_t* r, uint32_t addr) {
    asm volatile("ldmatrix.sync.aligned.m8n8.x4.shared.b16 {%0,%1,%2,%3}, [%4];"
                 : "=r"(r[0]), "=r"(r[1]), "=r"(r[2]), "=r"(r[3]) : "r"(addr));
}
__device__ __forceinline__ void mma16816(float* d, const uint32_t* a, uint32_t b0, uint32_t b1) {
    asm volatile("mma.sync.aligned.m16n8k16.row.col.f32.bf16.bf16.f32 "
                 "{%0,%1,%2,%3}, {%4,%5,%6,%7}, {%8,%9}, {%0,%1,%2,%3};"
                 : "+f"(d[0]), "+f"(d[1]), "+f"(d[2]), "+f"(d[3])
                 : "r"(a[0]), "r"(a[1]), "r"(a[2]), "r"(a[3]), "r"(b0), "r"(b1));
}

// ---------------- conversion kernels ----------------------------------------
__global__ void cvt_hilo_k(const float* __restrict__ s, __nv_bfloat16* __restrict__ h,
                           __nv_bfloat16* __restrict__ l, int n) {
    int i = blockIdx.x * 256 + threadIdx.x;
    if (i >= n) return;
    float x = s[i];
    __nv_bfloat16 hh = __float2bfloat16(x);
    h[i] = hh;
    l[i] = __float2bfloat16(x - __bfloat162float(hh));
}

__global__ void transpose_wconv_hilo(const float* __restrict__ Wc, __nv_bfloat16* __restrict__ h,
                                     __nv_bfloat16* __restrict__ l) {
    int idx = blockIdx.x * 256 + threadIdx.x;
    if (idx >= ND * 3 * ND) return;
    int o = idx / (3 * ND);
    int r = idx - o * 3 * ND;
    int kw = r >> 10;
    int i = r & 1023;
    float x = Wc[(size_t)o * 3 * ND + (size_t)i * 3 + kw];
    __nv_bfloat16 hh = __float2bfloat16(x);
    h[idx] = hh;
    l[idx] = __float2bfloat16(x - __bfloat162float(hh));
}

__global__ void copy_row0_hilo(const float* __restrict__ x, __nv_bfloat16* __restrict__ h,
                               __nv_bfloat16* __restrict__ l) {
    int idx = blockIdx.x * 256 + threadIdx.x;
    if (idx >= NB * ND) return;
    int b = idx >> 10, i = idx & 1023;
    float v = x[(size_t)b * NT * ND + i];
    __nv_bfloat16 hh = __float2bfloat16(v);
    h[(size_t)b * TK * ND + i] = hh;
    l[(size_t)b * TK * ND + i] = __float2bfloat16(v - __bfloat162float(hh));
}

// ---------------- HMMA bf16x3 GEMM -------------------------------------------
// C[m][n] = sum_k A[m][k]*W[n][k] in ~fp32 accuracy via bf16 hi/lo split:
//   Ahi*Bhi + Ahi*Blo + Alo*Bhi  (3 mma.sync per fragment pair)
// MODE 0: A rows contiguous stride K.  MODE 1 (conv): A row m -> x viewed at
//   ((m>>10)*3072 + (m&1023)*3)*1024, K=3072.
// EPI 0: fp32 out stride 1024.  EPI 1: bf16 hi/lo out with conv row remap +1.
// EPI 2: fp32 + bias.
template <int MODE, int EPI>
__global__ void __launch_bounds__(256, 1)
gemm_mma(const __nv_bfloat16* __restrict__ Ahi, const __nv_bfloat16* __restrict__ Alo,
         const __nv_bfloat16* __restrict__ Whi, const __nv_bfloat16* __restrict__ Wlo,
         float* __restrict__ Cf, __nv_bfloat16* __restrict__ Chi, __nv_bfloat16* __restrict__ Clo,
         const float* __restrict__ bias, int M, int K) {
    extern __shared__ __align__(128) __nv_bfloat16 sm[];
    uint32_t sb = smem_u32(sm);
    int tid = threadIdx.x;
    int bm = blockIdx.y * BM, bn = blockIdx.x * BN;
    int NKT = K / BKH;
    int lane = tid & 31, wid = tid >> 5;
    int wm = wid & 3, wn = wid >> 2;          // warp tile origin (wm*32, wn*64)

    float acc[2][8][4];
#pragma unroll
    for (int i = 0; i < 2; i++)
#pragma unroll
        for (int j = 0; j < 8; j++)
#pragma unroll
            for (int v = 0; v < 4; v++) acc[i][j][v] = 0.f;

    // ---- async stage loader: 2048 16B chunks, 8 per thread -----------------
    auto load_stage = [&](int kt, int s) {
        int k0 = kt * BKH;
        uint32_t sbase = sb + (uint32_t)s * STAGE_HALFS * 2;
#pragma unroll
        for (int t = 0; t < 8; t++) {
            int q = tid + t * 256;
            int tile = q >> 9;                 // 0=Ahi 1=Alo 2=Bhi 3=Blo
            int idx = q & 511;
            int r = idx >> 2, c = idx & 3;
            uint32_t dst = sbase + (uint32_t)tile * TILE_HALFS * 2 + r * 80 + c * 16;
            const __nv_bfloat16* src;
            if (tile < 2) {
                int row = bm + r;
                if (row > M - 1) row = M - 1;
                size_t off;
                if (MODE == 0) off = (size_t)row * K;
                else           off = ((size_t)(row >> 10) * NT + (size_t)(row & 1023) * 3) * ND;
                src = (tile ? Alo : Ahi) + off + k0 + c * 8;
            } else {
                src = (tile == 2 ? Whi : Wlo) + (size_t)(bn + r) * K + k0 + c * 8;
            }
            cpa16(dst, src);
        }
        asm volatile("cp.async.commit_group;" ::: "memory");
    };

    load_stage(0, 0);

    for (int kt = 0; kt < NKT; kt++) {
        if (kt + 1 < NKT) {
            load_stage(kt + 1, (kt + 1) & 1);
            asm volatile("cp.async.wait_group 1;" ::: "memory");
        } else {
            asm volatile("cp.async.wait_group 0;" ::: "memory");
        }
        __syncthreads();

        uint32_t st  = sb + (uint32_t)(kt & 1) * STAGE_HALFS * 2;
        uint32_t aHi = st;
        uint32_t aLo = st + TILE_HALFS * 2;
        uint32_t bHi = st + 2 * TILE_HALFS * 2;
        uint32_t bLo = st + 3 * TILE_HALFS * 2;

#pragma unroll
        for (int ks = 0; ks < 2; ks++) {
            // A fragments: rows wm*32 + {0,16} + lane&15; quads 2/3 at +16B
            uint32_t a_hi[2][4], a_lo[2][4];
            uint32_t aoff = (uint32_t)(wm * 32 + (lane & 15)) * 80 + ks * 32 + ((lane >> 4) << 4);
            ldsm4(a_hi[0], aHi + aoff);
            ldsm4(a_hi[1], aHi + aoff + 16 * 80);
            ldsm4(a_lo[0], aLo + aoff);
            ldsm4(a_lo[1], aLo + aoff + 16 * 80);

            uint32_t boff = (uint32_t)((lane & 7) + ((lane >> 4) << 3)) * 80
                          + (((lane >> 3) & 1) << 4) + ks * 32;
#pragma unroll
            for (int j = 0; j < 4; j++) {              // n-subtiles of 16 cols
                uint32_t b_hi[4], b_lo[4];
                uint32_t bo = boff + (uint32_t)(wn * 64 + j * 16) * 80;
                ldsm4(b_hi, bHi + bo);
                ldsm4(b_lo, bLo + bo);
#pragma unroll
                for (int p = 0; p < 2; p++) {          // two n8 groups per ldsm
                    int nj = j * 2 + p;
#pragma unroll
                    for (int mi = 0; mi < 2; mi++) {
                        mma16816(acc[mi][nj], a_hi[mi], b_hi[p * 2], b_hi[p * 2 + 1]);
                        mma16816(acc[mi][nj], a_hi[mi], b_lo[p * 2], b_lo[p * 2 + 1]);
                        mma16816(acc[mi][nj], a_lo[mi], b_hi[p * 2], b_hi[p * 2 + 1]);
                    }
                }
            }
        }
        __syncthreads();
    }

    // ---- epilogue ----------------------------------------------------------
    int tq = lane >> 2, tr = lane & 3;
#pragma unroll
    for (int mi = 0; mi < 2; mi++) {
#pragma unroll
        for (int half = 0; half < 2; half++) {         // c0/c1 vs c2/c3 (row +8)
            int row = bm + wm * 32 + mi * 16 + tq + half * 8;
            if (row >= M) continue;
#pragma unroll
            for (int nj = 0; nj < 8; nj++) {
                int col = bn + wn * 64 + nj * 8 + tr * 2;
                float v0 = acc[mi][nj][half * 2 + 0];
                float v1 = acc[mi][nj][half * 2 + 1];
                if (EPI == 1) {
                    int orow = ((row >> 10) * TK + (row & 1023) + 1);
                    __nv_bfloat16 h0 = __float2bfloat16(v0);
                    __nv_bfloat16 h1 = __float2bfloat16(v1);
                    __nv_bfloat162 hh; hh.x = h0; hh.y = h1;
                    *(__nv_bfloat162*)(Chi + (size_t)orow * ND + col) = hh;
                    __nv_bfloat162 ll;
                    ll.x = __float2bfloat16(v0 - __bfloat162float(h0));
                    ll.y = __float2bfloat16(v1 - __bfloat162float(h1));
                    *(__nv_bfloat162*)(Clo + (size_t)orow * ND + col) = ll;
                } else {
                    if (EPI == 2) { v0 += bias[col]; v1 += bias[col + 1]; }
                    float2 f2; f2.x = v0; f2.y = v1;
                    *(float2*)(Cf + (size_t)row * ND + col) = f2;
                }
            }
        }
    }
}

// ---------------- flash attention (fp32 CUDA cores) --------------------------
// grid: (T/128, B*H). thread t owns query q = q0+t. key k allowed iff 3k <= q.
__global__ void __launch_bounds__(128)
flash_attn(const float* __restrict__ Q, const float* __restrict__ Kb,
           const float* __restrict__ Vb, __nv_bfloat16* __restrict__ Ohi,
           __nv_bfloat16* __restrict__ Olo) {
    __shared__ float Ks[64][64];
    __shared__ float Vs[64][64];

    int bh = blockIdx.y;
    int b = bh >> 4, h = bh & 15;
    int q0 = blockIdx.x * 128;
    int t = threadIdx.x;
    int q = q0 + t;

    const float* qrow = Q + ((size_t)(b * NT + q)) * ND + h * HD;
    float qr[64];
#pragma unroll
    for (int d4 = 0; d4 < 16; d4++) {
        float4 f = ((const float4*)qrow)[d4];
        qr[d4 * 4 + 0] = f.x; qr[d4 * 4 + 1] = f.y;
        qr[d4 * 4 + 2] = f.z; qr[d4 * 4 + 3] = f.w;
    }

    float m_i = -1e30f, l_i = 0.f;
    float acc[64];
#pragma unroll
    for (int d = 0; d < 64; d++) acc[d] = 0.f;

    int kmax = q / 3;
    int kmax_blk = (q0 + 127) / 3;
    int ntiles = kmax_blk / 64 + 1;

    const float* kbase = Kb + (size_t)b * TK * ND + h * HD;
    const float* vbase = Vb + (size_t)b * TK * ND + h * HD;

    for (int tile = 0; tile < ntiles; tile++) {
        int kt0 = tile * 64;
        __syncthreads();
#pragma unroll
        for (int vv = 0; vv < 8; vv++) {
            int f = t + vv * 128;
            int j = f >> 4;
            int c = (f & 15) * 4;
            *(float4*)&Ks[j][c] = *(const float4*)(kbase + (size_t)(kt0 + j) * ND + c);
            *(float4*)&Vs[j][c] = *(const float4*)(vbase + (size_t)(kt0 + j) * ND + c);
        }
        __syncthreads();

        int jcnt = kmax - kt0 + 1;
        if (jcnt > 64) jcnt = 64;
        for (int j = 0; j < jcnt; j++) {
            const float4* kr = (const float4*)Ks[j];
            float s0 = 0.f, s1 = 0.f, s2 = 0.f, s3 = 0.f;
#pragma unroll
            for (int d4 = 0; d4 < 16; d4++) {
                float4 kk = kr[d4];
                s0 += qr[d4 * 4 + 0] * kk.x;
                s1 += qr[d4 * 4 + 1] * kk.y;
                s2 += qr[d4 * 4 + 2] * kk.z;
                s3 += qr[d4 * 4 + 3] * kk.w;
            }
            float s = ((s0 + s1) + (s2 + s3)) * 0.125f;
            if (s > m_i) {
                float corr = __expf(m_i - s);
                l_i *= corr;
#pragma unroll
                for (int d = 0; d < 64; d++) acc[d] *= corr;
                m_i = s;
            }
            float p = __expf(s - m_i);
            l_i += p;
            const float4* vr = (const float4*)Vs[j];
#pragma unroll
            for (int d4 = 0; d4 < 16; d4++) {
                float4 vvv = vr[d4];
                acc[d4 * 4 + 0] += p * vvv.x;
                acc[d4 * 4 + 1] += p * vvv.y;
                acc[d4 * 4 + 2] += p * vvv.z;
                acc[d4 * 4 + 3] += p * vvv.w;
            }
        }
    }

    float inv = 1.f / l_i;
    size_t ob = ((size_t)(b * NT + q)) * ND + h * HD;
    __nv_bfloat16* oh = Ohi + ob;
    __nv_bfloat16* ol = Olo + ob;
#pragma unroll
    for (int d = 0; d < 64; d += 2) {
        float v0 = acc[d] * inv;
        float v1 = acc[d + 1] * inv;
        __nv_bfloat16 h0 = __float2bfloat16(v0);
        __nv_bfloat16 h1 = __float2bfloat16(v1);
        __nv_bfloat162 hh; hh.x = h0; hh.y = h1;
        *(__nv_bfloat162*)(oh + d) = hh;
        __nv_bfloat162 ll;
        ll.x = __float2bfloat16(v0 - __bfloat162float(h0));
        ll.y = __float2bfloat16(v1 - __bfloat162float(h1));
        *(__nv_bfloat162*)(ol + d) = ll;
    }
}

// ---------------- launch ------------------------------------------------------
extern "C" void kernel_launch(void* const* d_in, const int* in_sizes, int n_in,
                              void* d_out, int out_size) {
    const float* x     = (const float*)d_in[0];
    const float* Wq    = (const float*)d_in[1];
    const float* Wk    = (const float*)d_in[2];
    const float* Wv    = (const float*)d_in[3];
    const float* Wo    = (const float*)d_in[4];
    const float* bo    = (const float*)d_in[5];
    const float* Wconv = (const float*)d_in[6];
    float* out = (float*)d_out;

    __nv_bfloat16 *xhi, *xlo, *khi, *klo, *ohi, *olo;
    __nv_bfloat16 *wqhi, *wqlo, *wkhi, *wklo, *wvhi, *wvlo, *wohi, *wolo, *wchi, *wclo;
    float *pq, *pk, *pv;
    cudaGetSymbolAddress((void**)&xhi, g_xhi);   cudaGetSymbolAddress((void**)&xlo, g_xlo);
    cudaGetSymbolAddress((void**)&khi, g_khi);   cudaGetSymbolAddress((void**)&klo, g_klo);
    cudaGetSymbolAddress((void**)&ohi, g_ohi);   cudaGetSymbolAddress((void**)&olo, g_olo);
    cudaGetSymbolAddress((void**)&pq, g_q);
    cudaGetSymbolAddress((void**)&pk, g_k);
    cudaGetSymbolAddress((void**)&pv, g_v);
    cudaGetSymbolAddress((void**)&wqhi, g_wqhi); cudaGetSymbolAddress((void**)&wqlo, g_wqlo);
    cudaGetSymbolAddress((void**)&wkhi, g_wkhi); cudaGetSymbolAddress((void**)&wklo, g_wklo);
    cudaGetSymbolAddress((void**)&wvhi, g_wvhi); cudaGetSymbolAddress((void**)&wvlo, g_wvlo);
    cudaGetSymbolAddress((void**)&wohi, g_wohi); cudaGetSymbolAddress((void**)&wolo, g_wolo);
    cudaGetSymbolAddress((void**)&wchi, g_wchi); cudaGetSymbolAddress((void**)&wclo, g_wclo);

    cudaFuncSetAttribute(gemm_mma<0, 0>, cudaFuncAttributeMaxDynamicSharedMemorySize, GEMM_SMEM);
    cudaFuncSetAttribute(gemm_mma<1, 1>, cudaFuncAttributeMaxDynamicSharedMemorySize, GEMM_SMEM);
    cudaFuncSetAttribute(gemm_mma<0, 2>, cudaFuncAttributeMaxDynamicSharedMemorySize, GEMM_SMEM);

    // 1. hi/lo conversions of x and weights
    int nx = NB * NT * ND;
    cvt_hilo_k<<<(nx + 255) / 256, 256>>>(x, xhi, xlo, nx);
    cvt_hilo_k<<<(ND * ND + 255) / 256, 256>>>(Wq, wqhi, wqlo, ND * ND);
    cvt_hilo_k<<<(ND * ND + 255) / 256, 256>>>(Wk, wkhi, wklo, ND * ND);
    cvt_hilo_k<<<(ND * ND + 255) / 256, 256>>>(Wv, wvhi, wvlo, ND * ND);
    cvt_hilo_k<<<(ND * ND + 255) / 256, 256>>>(Wo, wohi, wolo, ND * ND);
    transpose_wconv_hilo<<<(ND * 3 * ND + 255) / 256, 256>>>(Wconv, wchi, wclo);
    copy_row0_hilo<<<(NB * ND + 255) / 256, 256>>>(x, khi, klo);

    // 2. conv pooling as GEMM (x viewed as 4096 x 3072 contiguous) -> ktmp hi/lo
    gemm_mma<1, 1><<<dim3(8, 32), 256, GEMM_SMEM>>>(xhi, xlo, wchi, wclo,
                                                    nullptr, khi, klo, nullptr, NB * ND, 3 * ND);

    // 3. projections -> fp32 q/k/v for flash
    gemm_mma<0, 0><<<dim3(8, 96), 256, GEMM_SMEM>>>(xhi, xlo, wqhi, wqlo,
                                                    pq, nullptr, nullptr, nullptr, NB * NT, ND);
    gemm_mma<0, 0><<<dim3(8, 33), 256, GEMM_SMEM>>>(khi, klo, wkhi, wklo,
                                                    pk, nullptr, nullptr, nullptr, NB * TK, ND);
    gemm_mma<0, 0><<<dim3(8, 33), 256, GEMM_SMEM>>>(khi, klo, wvhi, wvlo,
                                                    pv, nullptr, nullptr, nullptr, NB * TK, ND);

    // 4. masked flash attention -> o hi/lo
    flash_attn<<<dim3(NT / 128, NB * NH), 128>>>(pq, pk, pv, ohi, olo);

    // 5. output projection + bias -> d_out
    gemm_mma<0, 2><<<dim3(8, 96), 256, GEMM_SMEM>>>(ohi, olo, wohi, wolo,
                                                    out, nullptr, nullptr, bo, NB * NT, ND);
}

// round 6
// speedup vs baseline: 2.5517x; 1.5877x over previous
#include <cuda_runtime.h>
#include <cuda_bf16.h>
#include <cstdint>

#define NB 4
#define NT 3072
#define ND 1024
#define NH 16
#define HD 64
#define TK 1025   // pooled K/V length: 1 + 3072/3

// GEMM tiling: 128x128 CTA tile, BK=32 halfs, 8 warps (4M x 2N), warp tile 32x64
#define BM 128
#define BN 128
#define BKH 32
#define TSTRIDE 40
#define TILE_HALFS (128 * TSTRIDE)
#define STAGE_HALFS (4 * TILE_HALFS)
#define GEMM_SMEM (2 * STAGE_HALFS * 2)   // 81920 B

// Flash tiling: 128 q x 64 keys, 8 warps (1 m16 each), stride 72 halfs (144B)
#define FS_STRIDE 144                      // bytes per row
#define FS_TILE_B (64 * FS_STRIDE)         // 9216 B per 64x64 bf16 tile
#define FS_STAGE_B (4 * FS_TILE_B)         // Khi,Klo,Vhi,Vlo = 36864 B
#define FLASH_SMEM (2 * FS_STAGE_B)        // 73728 B

// ---------------- scratch (device globals: no allocations allowed) ----------
__device__ __align__(256) __nv_bfloat16 g_xhi[NB * NT * ND];
__device__ __align__(256) __nv_bfloat16 g_xlo[NB * NT * ND];
__device__ __align__(256) __nv_bfloat16 g_khi[NB * TK * ND];   // pooled stream
__device__ __align__(256) __nv_bfloat16 g_klo[NB * TK * ND];
__device__ __align__(256) __nv_bfloat16 g_ohi[NB * NT * ND];   // attention out
__device__ __align__(256) __nv_bfloat16 g_olo[NB * NT * ND];
__device__ __align__(256) __nv_bfloat16 g_qh[NB * NT * ND], g_ql[NB * NT * ND];
__device__ __align__(256) __nv_bfloat16 g_kh[NB * TK * ND], g_kl[NB * TK * ND];
__device__ __align__(256) __nv_bfloat16 g_vh[NB * TK * ND], g_vl[NB * TK * ND];
__device__ __align__(256) __nv_bfloat16 g_wqhi[ND * ND], g_wqlo[ND * ND];
__device__ __align__(256) __nv_bfloat16 g_wkhi[ND * ND], g_wklo[ND * ND];
__device__ __align__(256) __nv_bfloat16 g_wvhi[ND * ND], g_wvlo[ND * ND];
__device__ __align__(256) __nv_bfloat16 g_wohi[ND * ND], g_wolo[ND * ND];
__device__ __align__(256) __nv_bfloat16 g_wchi[ND * 3 * ND], g_wclo[ND * 3 * ND];

// ---------------- PTX helpers ------------------------------------------------
__device__ __forceinline__ uint32_t smem_u32(const void* p) {
    uint32_t a;
    asm("{ .reg .u64 t; cvta.to.shared.u64 t, %1; cvt.u32.u64 %0, t; }" : "=r"(a) : "l"(p));
    return a;
}
__device__ __forceinline__ void cpa16(uint32_t dst, const void* src) {
    asm volatile("cp.async.cg.shared.global [%0], [%1], 16;" :: "r"(dst), "l"(src) : "memory");
}
__device__ __forceinline__ void ldsm4(uint32_t* r, uint32_t addr) {
    asm volatile("ldmatrix.sync.aligned.m8n8.x4.shared.b16 {%0,%1,%2,%3}, [%4];"
                 : "=r"(r[0]), "=r"(r[1]), "=r"(r[2]), "=r"(r[3]) : "r"(addr));
}
__device__ __forceinline__ void ldsm4t(uint32_t* r, uint32_t addr) {
    asm volatile("ldmatrix.sync.aligned.m8n8.x4.trans.shared.b16 {%0,%1,%2,%3}, [%4];"
                 : "=r"(r[0]), "=r"(r[1]), "=r"(r[2]), "=r"(r[3]) : "r"(addr));
}
__device__ __forceinline__ void mma16816(float* d, const uint32_t* a, uint32_t b0, uint32_t b1) {
    asm volatile("mma.sync.aligned.m16n8k16.row.col.f32.bf16.bf16.f32 "
                 "{%0,%1,%2,%3}, {%4,%5,%6,%7}, {%8,%9}, {%0,%1,%2,%3};"
                 : "+f"(d[0]), "+f"(d[1]), "+f"(d[2]), "+f"(d[3])
                 : "r"(a[0]), "r"(a[1]), "r"(a[2]), "r"(a[3]), "r"(b0), "r"(b1));
}
__device__ __forceinline__ uint32_t packbf(__nv_bfloat16 a, __nv_bfloat16 b) {
    __nv_bfloat162 t; t.x = a; t.y = b;
    return *(uint32_t*)&t;
}

// ---------------- conversion kernels ----------------------------------------
__global__ void cvt_hilo_k(const float* __restrict__ s, __nv_bfloat16* __restrict__ h,
                           __nv_bfloat16* __restrict__ l, int n) {
    int i = blockIdx.x * 256 + threadIdx.x;
    if (i >= n) return;
    float x = s[i];
    __nv_bfloat16 hh = __float2bfloat16(x);
    h[i] = hh;
    l[i] = __float2bfloat16(x - __bfloat162float(hh));
}

__global__ void transpose_wconv_hilo(const float* __restrict__ Wc, __nv_bfloat16* __restrict__ h,
                                     __nv_bfloat16* __restrict__ l) {
    int idx = blockIdx.x * 256 + threadIdx.x;
    if (idx >= ND * 3 * ND) return;
    int o = idx / (3 * ND);
    int r = idx - o * 3 * ND;
    int kw = r >> 10;
    int i = r & 1023;
    float x = Wc[(size_t)o * 3 * ND + (size_t)i * 3 + kw];
    __nv_bfloat16 hh = __float2bfloat16(x);
    h[idx] = hh;
    l[idx] = __float2bfloat16(x - __bfloat162float(hh));
}

__global__ void copy_row0_hilo(const float* __restrict__ x, __nv_bfloat16* __restrict__ h,
                               __nv_bfloat16* __restrict__ l) {
    int idx = blockIdx.x * 256 + threadIdx.x;
    if (idx >= NB * ND) return;
    int b = idx >> 10, i = idx & 1023;
    float v = x[(size_t)b * NT * ND + i];
    __nv_bfloat16 hh = __float2bfloat16(v);
    h[(size_t)b * TK * ND + i] = hh;
    l[(size_t)b * TK * ND + i] = __float2bfloat16(v - __bfloat162float(hh));
}

// ---------------- HMMA bf16x3 GEMM -------------------------------------------
// C[m][n] = sum_k A[m][k]*W[n][k], ~fp32 via Ahi*Bhi + Ahi*Blo + Alo*Bhi.
// MODE 0: A rows contiguous stride K.  MODE 1 (conv): A row m -> x at
//   ((m>>10)*3072 + (m&1023)*3)*1024, K=3072.
// EPI 0: fp32 out. EPI 1: bf16 hi/lo with conv row remap +1. EPI 2: fp32+bias.
// EPI 3: bf16 hi/lo direct rows.
template <int MODE, int EPI>
__global__ void __launch_bounds__(256, 1)
gemm_mma(const __nv_bfloat16* __restrict__ Ahi, const __nv_bfloat16* __restrict__ Alo,
         const __nv_bfloat16* __restrict__ Whi, const __nv_bfloat16* __restrict__ Wlo,
         float* __restrict__ Cf, __nv_bfloat16* __restrict__ Chi, __nv_bfloat16* __restrict__ Clo,
         const float* __restrict__ bias, int M, int K) {
    extern __shared__ __align__(128) __nv_bfloat16 sm[];
    uint32_t sb = smem_u32(sm);
    int tid = threadIdx.x;
    int bm = blockIdx.y * BM, bn = blockIdx.x * BN;
    int NKT = K / BKH;
    int lane = tid & 31, wid = tid >> 5;
    int wm = wid & 3, wn = wid >> 2;

    float acc[2][8][4];
#pragma unroll
    for (int i = 0; i < 2; i++)
#pragma unroll
        for (int j = 0; j < 8; j++)
#pragma unroll
            for (int v = 0; v < 4; v++) acc[i][j][v] = 0.f;

    auto load_stage = [&](int kt, int s) {
        int k0 = kt * BKH;
        uint32_t sbase = sb + (uint32_t)s * STAGE_HALFS * 2;
#pragma unroll
        for (int t = 0; t < 8; t++) {
            int q = tid + t * 256;
            int tile = q >> 9;
            int idx = q & 511;
            int r = idx >> 2, c = idx & 3;
            uint32_t dst = sbase + (uint32_t)tile * TILE_HALFS * 2 + r * 80 + c * 16;
            const __nv_bfloat16* src;
            if (tile < 2) {
                int row = bm + r;
                if (row > M - 1) row = M - 1;
                size_t off;
                if (MODE == 0) off = (size_t)row * K;
                else           off = ((size_t)(row >> 10) * NT + (size_t)(row & 1023) * 3) * ND;
                src = (tile ? Alo : Ahi) + off + k0 + c * 8;
            } else {
                src = (tile == 2 ? Whi : Wlo) + (size_t)(bn + r) * K + k0 + c * 8;
            }
            cpa16(dst, src);
        }
        asm volatile("cp.async.commit_group;" ::: "memory");
    };

    load_stage(0, 0);

    for (int kt = 0; kt < NKT; kt++) {
        if (kt + 1 < NKT) {
            load_stage(kt + 1, (kt + 1) & 1);
            asm volatile("cp.async.wait_group 1;" ::: "memory");
        } else {
            asm volatile("cp.async.wait_group 0;" ::: "memory");
        }
        __syncthreads();

        uint32_t st  = sb + (uint32_t)(kt & 1) * STAGE_HALFS * 2;
        uint32_t aHi = st;
        uint32_t aLo = st + TILE_HALFS * 2;
        uint32_t bHi = st + 2 * TILE_HALFS * 2;
        uint32_t bLo = st + 3 * TILE_HALFS * 2;

#pragma unroll
        for (int ks = 0; ks < 2; ks++) {
            uint32_t a_hi[2][4], a_lo[2][4];
            uint32_t aoff = (uint32_t)(wm * 32 + (lane & 15)) * 80 + ks * 32 + ((lane >> 4) << 4);
            ldsm4(a_hi[0], aHi + aoff);
            ldsm4(a_hi[1], aHi + aoff + 16 * 80);
            ldsm4(a_lo[0], aLo + aoff);
            ldsm4(a_lo[1], aLo + aoff + 16 * 80);

            uint32_t boff = (uint32_t)((lane & 7) + ((lane >> 4) << 3)) * 80
                          + (((lane >> 3) & 1) << 4) + ks * 32;
#pragma unroll
            for (int j = 0; j < 4; j++) {
                uint32_t b_hi[4], b_lo[4];
                uint32_t bo = boff + (uint32_t)(wn * 64 + j * 16) * 80;
                ldsm4(b_hi, bHi + bo);
                ldsm4(b_lo, bLo + bo);
#pragma unroll
                for (int p = 0; p < 2; p++) {
                    int nj = j * 2 + p;
#pragma unroll
                    for (int mi = 0; mi < 2; mi++) {
                        mma16816(acc[mi][nj], a_hi[mi], b_hi[p * 2], b_hi[p * 2 + 1]);
                        mma16816(acc[mi][nj], a_hi[mi], b_lo[p * 2], b_lo[p * 2 + 1]);
                        mma16816(acc[mi][nj], a_lo[mi], b_hi[p * 2], b_hi[p * 2 + 1]);
                    }
                }
            }
        }
        __syncthreads();
    }

    int tq = lane >> 2, tr = lane & 3;
#pragma unroll
    for (int mi = 0; mi < 2; mi++) {
#pragma unroll
        for (int half = 0; half < 2; half++) {
            int row = bm + wm * 32 + mi * 16 + tq + half * 8;
            if (row >= M) continue;
#pragma unroll
            for (int nj = 0; nj < 8; nj++) {
                int col = bn + wn * 64 + nj * 8 + tr * 2;
                float v0 = acc[mi][nj][half * 2 + 0];
                float v1 = acc[mi][nj][half * 2 + 1];
                if (EPI == 1 || EPI == 3) {
                    int orow = (EPI == 1) ? ((row >> 10) * TK + (row & 1023) + 1) : row;
                    __nv_bfloat16 h0 = __float2bfloat16(v0);
                    __nv_bfloat16 h1 = __float2bfloat16(v1);
                    *(__nv_bfloat162*)(Chi + (size_t)orow * ND + col) = *(__nv_bfloat162*)&(uint32_t&)*(uint32_t[]){packbf(h0, h1)};
                    uint32_t lw = packbf(__float2bfloat16(v0 - __bfloat162float(h0)),
                                         __float2bfloat16(v1 - __bfloat162float(h1)));
                    *(uint32_t*)(Clo + (size_t)orow * ND + col) = lw;
                    uint32_t hw = packbf(h0, h1);
                    *(uint32_t*)(Chi + (size_t)orow * ND + col) = hw;
                } else {
                    if (EPI == 2) { v0 += bias[col]; v1 += bias[col + 1]; }
                    float2 f2; f2.x = v0; f2.y = v1;
                    *(float2*)(Cf + (size_t)row * ND + col) = f2;
                }
            }
        }
    }
}

// ---------------- HMMA flash attention ---------------------------------------
// grid (24, 64): 128-q tile per CTA, 8 warps (one m16 each), 64-key tiles.
// S = QK^T via 3-mma hi/lo; online softmax in fragments; P split hi/lo; PV 3-mma.
__global__ void __launch_bounds__(256, 1)
flash_mma(const __nv_bfloat16* __restrict__ Qh, const __nv_bfloat16* __restrict__ Ql,
          const __nv_bfloat16* __restrict__ Kh, const __nv_bfloat16* __restrict__ Kl,
          const __nv_bfloat16* __restrict__ Vh, const __nv_bfloat16* __restrict__ Vl,
          __nv_bfloat16* __restrict__ Ohi, __nv_bfloat16* __restrict__ Olo) {
    extern __shared__ __align__(128) char fsm[];
    uint32_t sb = smem_u32(fsm);
    int tid = threadIdx.x, lane = tid & 31, w = tid >> 5;
    int bh = blockIdx.y;
    int b = bh >> 4, h = bh & 15;
    int q0 = blockIdx.x * 128;

    const __nv_bfloat16* qhg = Qh + ((size_t)b * NT + q0) * ND + h * HD;
    const __nv_bfloat16* qlg = Ql + ((size_t)b * NT + q0) * ND + h * HD;
    const __nv_bfloat16* khg = Kh + (size_t)b * TK * ND + h * HD;
    const __nv_bfloat16* klg = Kl + (size_t)b * TK * ND + h * HD;
    const __nv_bfloat16* vhg = Vh + (size_t)b * TK * ND + h * HD;
    const __nv_bfloat16* vlg = Vl + (size_t)b * TK * ND + h * HD;

    // ---- stage Q (128x64 hi/lo) into smem, extract A fragments -------------
#pragma unroll
    for (int t = 0; t < 8; t++) {
        int idx = tid + (t & 3) * 256;          // 0..1023
        int r = idx >> 3, c = idx & 7;
        const __nv_bfloat16* g = (t < 4) ? qhg : qlg;
        cpa16(sb + (t < 4 ? 0 : 18432) + r * FS_STRIDE + c * 16,
              g + (size_t)r * ND + c * 8);
    }
    asm volatile("cp.async.commit_group;" ::: "memory");
    asm volatile("cp.async.wait_group 0;" ::: "memory");
    __syncthreads();

    uint32_t qfh[4][4], qfl[4][4];
    {
        uint32_t aoff = (uint32_t)(w * 16 + (lane & 15)) * FS_STRIDE + ((lane >> 4) << 4);
#pragma unroll
        for (int kc = 0; kc < 4; kc++) {
            ldsm4(qfh[kc], sb + aoff + kc * 32);
            ldsm4(qfl[kc], sb + 18432 + aoff + kc * 32);
        }
    }
    __syncthreads();

    float m0 = -1e30f, m1 = -1e30f, l0 = 0.f, l1 = 0.f;
    float ao[8][4];
#pragma unroll
    for (int j = 0; j < 8; j++)
#pragma unroll
        for (int v = 0; v < 4; v++) ao[j][v] = 0.f;

    int kmax_blk = (q0 + 127) / 3;
    int ntiles = kmax_blk / 64 + 1;
    int qwmax = q0 + w * 16 + 15;
    int g8 = lane >> 2, tr2 = (lane & 3) * 2;
    int qa = q0 + w * 16 + g8, qb = qa + 8;

    auto load_kv = [&](int kt, int s) {
        uint32_t bse = sb + (uint32_t)s * FS_STAGE_B;
        size_t koff = (size_t)kt * 64 * ND;
#pragma unroll
        for (int t = 0; t < 8; t++) {
            int idx = tid + (t & 1) * 256;      // 0..511
            int r = idx >> 3, c = idx & 7;
            const __nv_bfloat16* g =
                (t < 2) ? khg : (t < 4) ? klg : (t < 6) ? vhg : vlg;
            cpa16(bse + (uint32_t)(t >> 1) * FS_TILE_B + r * FS_STRIDE + c * 16,
                  g + koff + (size_t)r * ND + c * 8);
        }
        asm volatile("cp.async.commit_group;" ::: "memory");
    };

    load_kv(0, 0);

    for (int kt = 0; kt < ntiles; kt++) {
        if (kt + 1 < ntiles) {
            load_kv(kt + 1, (kt + 1) & 1);
            asm volatile("cp.async.wait_group 1;" ::: "memory");
        } else {
            asm volatile("cp.async.wait_group 0;" ::: "memory");
        }
        __syncthreads();
        int kt0 = kt * 64;
        if (3 * kt0 <= qwmax) {
            uint32_t st = sb + (uint32_t)(kt & 1) * FS_STAGE_B;

            // ---- S = Q K^T (hi/lo x3) --------------------------------------
            float sacc[8][4];
#pragma unroll
            for (int j = 0; j < 8; j++)
#pragma unroll
                for (int v = 0; v < 4; v++) sacc[j][v] = 0.f;

#pragma unroll
            for (int njp = 0; njp < 4; njp++) {
#pragma unroll
                for (int kc = 0; kc < 4; kc++) {
                    uint32_t boff = (uint32_t)(njp * 16 + (lane & 7) + ((lane >> 4) << 3)) * FS_STRIDE
                                  + kc * 32 + (((lane >> 3) & 1) << 4);
                    uint32_t bkh[4], bkl[4];
                    ldsm4(bkh, st + boff);
                    ldsm4(bkl, st + FS_TILE_B + boff);
#pragma unroll
                    for (int p = 0; p < 2; p++) {
                        mma16816(sacc[njp * 2 + p], qfh[kc], bkh[p * 2], bkh[p * 2 + 1]);
                        mma16816(sacc[njp * 2 + p], qfh[kc], bkl[p * 2], bkl[p * 2 + 1]);
                        mma16816(sacc[njp * 2 + p], qfl[kc], bkh[p * 2], bkh[p * 2 + 1]);
                    }
                }
            }

            // ---- scale + mask + online softmax -----------------------------
            float rm0 = -1e30f, rm1 = -1e30f;
#pragma unroll
            for (int nj = 0; nj < 8; nj++) {
                int key = kt0 + nj * 8 + tr2;
                float s0 = sacc[nj][0] * 0.125f; if (3 * key > qa) s0 = -1e30f;
                float s1 = sacc[nj][1] * 0.125f; if (3 * (key + 1) > qa) s1 = -1e30f;
                float s2 = sacc[nj][2] * 0.125f; if (3 * key > qb) s2 = -1e30f;
                float s3 = sacc[nj][3] * 0.125f; if (3 * (key + 1) > qb) s3 = -1e30f;
                sacc[nj][0] = s0; sacc[nj][1] = s1; sacc[nj][2] = s2; sacc[nj][3] = s3;
                rm0 = fmaxf(rm0, fmaxf(s0, s1));
                rm1 = fmaxf(rm1, fmaxf(s2, s3));
            }
            rm0 = fmaxf(rm0, __shfl_xor_sync(0xffffffffu, rm0, 1));
            rm0 = fmaxf(rm0, __shfl_xor_sync(0xffffffffu, rm0, 2));
            rm1 = fmaxf(rm1, __shfl_xor_sync(0xffffffffu, rm1, 1));
            rm1 = fmaxf(rm1, __shfl_xor_sync(0xffffffffu, rm1, 2));
            float nm0 = fmaxf(m0, rm0), nm1 = fmaxf(m1, rm1);
            float c0 = __expf(m0 - nm0), c1 = __expf(m1 - nm1);
            m0 = nm0; m1 = nm1;

            float ls0 = 0.f, ls1 = 0.f;
#pragma unroll
            for (int nj = 0; nj < 8; nj++) {
                float p0 = __expf(sacc[nj][0] - m0);
                float p1 = __expf(sacc[nj][1] - m0);
                float p2 = __expf(sacc[nj][2] - m1);
                float p3 = __expf(sacc[nj][3] - m1);
                sacc[nj][0] = p0; sacc[nj][1] = p1; sacc[nj][2] = p2; sacc[nj][3] = p3;
                ls0 += p0 + p1; ls1 += p2 + p3;
            }
            ls0 += __shfl_xor_sync(0xffffffffu, ls0, 1);
            ls0 += __shfl_xor_sync(0xffffffffu, ls0, 2);
            ls1 += __shfl_xor_sync(0xffffffffu, ls1, 1);
            ls1 += __shfl_xor_sync(0xffffffffu, ls1, 2);
            l0 = l0 * c0 + ls0;
            l1 = l1 * c1 + ls1;
#pragma unroll
            for (int nj = 0; nj < 8; nj++) {
                ao[nj][0] *= c0; ao[nj][1] *= c0;
                ao[nj][2] *= c1; ao[nj][3] *= c1;
            }

            // ---- P -> bf16 hi/lo A fragments -------------------------------
            uint32_t pah[4][4], pal[4][4];
#pragma unroll
            for (int kc = 0; kc < 4; kc++) {
#pragma unroll
                for (int rr = 0; rr < 4; rr++) {
                    int nj = kc * 2 + (rr >> 1);
                    int vb = (rr & 1) * 2;
                    float pa = sacc[nj][vb], pb = sacc[nj][vb + 1];
                    __nv_bfloat16 ha = __float2bfloat16(pa);
                    __nv_bfloat16 hb = __float2bfloat16(pb);
                    pah[kc][rr] = packbf(ha, hb);
                    pal[kc][rr] = packbf(__float2bfloat16(pa - __bfloat162float(ha)),
                                         __float2bfloat16(pb - __bfloat162float(hb)));
                }
            }

            // ---- O += P V (hi/lo x3) ---------------------------------------
            uint32_t vbh = st + 2 * FS_TILE_B;
            uint32_t vbl = st + 3 * FS_TILE_B;
#pragma unroll
            for (int njp = 0; njp < 4; njp++) {
#pragma unroll
                for (int kc = 0; kc < 4; kc++) {
                    uint32_t voff = (uint32_t)(kc * 16 + (lane & 7) + (((lane >> 3) & 1) << 3)) * FS_STRIDE
                                  + (njp * 16 + (((lane >> 4) & 1) << 3)) * 2;
                    uint32_t bv[4], bw[4];
                    ldsm4t(bv, vbh + voff);
                    ldsm4t(bw, vbl + voff);
#pragma unroll
                    for (int p = 0; p < 2; p++) {
                        mma16816(ao[njp * 2 + p], pah[kc], bv[p * 2], bv[p * 2 + 1]);
                        mma16816(ao[njp * 2 + p], pal[kc], bv[p * 2], bv[p * 2 + 1]);
                        mma16816(ao[njp * 2 + p], pah[kc], bw[p * 2], bw[p * 2 + 1]);
                    }
                }
            }
        }
        __syncthreads();
    }

    // ---- write O hi/lo ------------------------------------------------------
    float i0 = 1.f / l0, i1 = 1.f / l1;
    size_t rowa = ((size_t)b * NT + qa) * ND + h * HD;
    size_t rowb = rowa + (size_t)8 * ND;
#pragma unroll
    for (int nj = 0; nj < 8; nj++) {
        int col = nj * 8 + tr2;
        float v0 = ao[nj][0] * i0, v1 = ao[nj][1] * i0;
        float v2 = ao[nj][2] * i1, v3 = ao[nj][3] * i1;
        __nv_bfloat16 h0 = __float2bfloat16(v0), h1 = __float2bfloat16(v1);
        __nv_bfloat16 h2 = __float2bfloat16(v2), h3 = __float2bfloat16(v3);
        *(uint32_t*)(Ohi + rowa + col) = packbf(h0, h1);
        *(uint32_t*)(Olo + rowa + col) = packbf(__float2bfloat16(v0 - __bfloat162float(h0)),
                                                __float2bfloat16(v1 - __bfloat162float(h1)));
        *(uint32_t*)(Ohi + rowb + col) = packbf(h2, h3);
        *(uint32_t*)(Olo + rowb + col) = packbf(__float2bfloat16(v2 - __bfloat162float(h2)),
                                                __float2bfloat16(v3 - __bfloat162float(h3)));
    }
}

// ---------------- launch ------------------------------------------------------
extern "C" void kernel_launch(void* const* d_in, const int* in_sizes, int n_in,
                              void* d_out, int out_size) {
    const float* x     = (const float*)d_in[0];
    const float* Wq    = (const float*)d_in[1];
    const float* Wk    = (const float*)d_in[2];
    const float* Wv    = (const float*)d_in[3];
    const float* Wo    = (const float*)d_in[4];
    const float* bo    = (const float*)d_in[5];
    const float* Wconv = (const float*)d_in[6];
    float* out = (float*)d_out;

    __nv_bfloat16 *xhi, *xlo, *khi, *klo, *ohi, *olo;
    __nv_bfloat16 *qh, *ql, *kh, *kl, *vh, *vl;
    __nv_bfloat16 *wqhi, *wqlo, *wkhi, *wklo, *wvhi, *wvlo, *wohi, *wolo, *wchi, *wclo;
    cudaGetSymbolAddress((void**)&xhi, g_xhi);   cudaGetSymbolAddress((void**)&xlo, g_xlo);
    cudaGetSymbolAddress((void**)&khi, g_khi);   cudaGetSymbolAddress((void**)&klo, g_klo);
    cudaGetSymbolAddress((void**)&ohi, g_ohi);   cudaGetSymbolAddress((void**)&olo, g_olo);
    cudaGetSymbolAddress((void**)&qh, g_qh);     cudaGetSymbolAddress((void**)&ql, g_ql);
    cudaGetSymbolAddress((void**)&kh, g_kh);     cudaGetSymbolAddress((void**)&kl, g_kl);
    cudaGetSymbolAddress((void**)&vh, g_vh);     cudaGetSymbolAddress((void**)&vl, g_vl);
    cudaGetSymbolAddress((void**)&wqhi, g_wqhi); cudaGetSymbolAddress((void**)&wqlo, g_wqlo);
    cudaGetSymbolAddress((void**)&wkhi, g_wkhi); cudaGetSymbolAddress((void**)&wklo, g_wklo);
    cudaGetSymbolAddress((void**)&wvhi, g_wvhi); cudaGetSymbolAddress((void**)&wvlo, g_wvlo);
    cudaGetSymbolAddress((void**)&wohi, g_wohi); cudaGetSymbolAddress((void**)&wolo, g_wolo);
    cudaGetSymbolAddress((void**)&wchi, g_wchi); cudaGetSymbolAddress((void**)&wclo, g_wclo);

    cudaFuncSetAttribute(gemm_mma<0, 0>, cudaFuncAttributeMaxDynamicSharedMemorySize, GEMM_SMEM);
    cudaFuncSetAttribute(gemm_mma<1, 1>, cudaFuncAttributeMaxDynamicSharedMemorySize, GEMM_SMEM);
    cudaFuncSetAttribute(gemm_mma<0, 2>, cudaFuncAttributeMaxDynamicSharedMemorySize, GEMM_SMEM);
    cudaFuncSetAttribute(gemm_mma<0, 3>, cudaFuncAttributeMaxDynamicSharedMemorySize, GEMM_SMEM);
    cudaFuncSetAttribute(flash_mma, cudaFuncAttributeMaxDynamicSharedMemorySize, FLASH_SMEM);

    // 1. hi/lo conversions
    int nx = NB * NT * ND;
    cvt_hilo_k<<<(nx + 255) / 256, 256>>>(x, xhi, xlo, nx);
    cvt_hilo_k<<<(ND * ND + 255) / 256, 256>>>(Wq, wqhi, wqlo, ND * ND);
    cvt_hilo_k<<<(ND * ND + 255) / 256, 256>>>(Wk, wkhi, wklo, ND * ND);
    cvt_hilo_k<<<(ND * ND + 255) / 256, 256>>>(Wv, wvhi, wvlo, ND * ND);
    cvt_hilo_k<<<(ND * ND + 255) / 256, 256>>>(Wo, wohi, wolo, ND * ND);
    transpose_wconv_hilo<<<(ND * 3 * ND + 255) / 256, 256>>>(Wconv, wchi, wclo);
    copy_row0_hilo<<<(NB * ND + 255) / 256, 256>>>(x, khi, klo);

    // 2. conv pooling as GEMM -> ktmp hi/lo
    gemm_mma<1, 1><<<dim3(8, 32), 256, GEMM_SMEM>>>(xhi, xlo, wchi, wclo,
                                                    nullptr, khi, klo, nullptr, NB * ND, 3 * ND);

    // 3. projections -> bf16 hi/lo q/k/v
    gemm_mma<0, 3><<<dim3(8, 96), 256, GEMM_SMEM>>>(xhi, xlo, wqhi, wqlo,
                                                    nullptr, qh, ql, nullptr, NB * NT, ND);
    gemm_mma<0, 3><<<dim3(8, 33), 256, GEMM_SMEM>>>(khi, klo, wkhi, wklo,
                                                    nullptr, kh, kl, nullptr, NB * TK, ND);
    gemm_mma<0, 3><<<dim3(8, 33), 256, GEMM_SMEM>>>(khi, klo, wvhi, wvlo,
                                                    nullptr, vh, vl, nullptr, NB * TK, ND);

    // 4. HMMA masked flash attention -> o hi/lo
    flash_mma<<<dim3(NT / 128, NB * NH), 256, FLASH_SMEM>>>(qh, ql, kh, kl, vh, vl, ohi, olo);

    // 5. output projection + bias -> d_out
    gemm_mma<0, 2><<<dim3(8, 96), 256, GEMM_SMEM>>>(ohi, olo, wohi, wolo,
                                                    out, nullptr, nullptr, bo, NB * NT, ND);
}